// round 14
// baseline (speedup 1.0000x reference)
#include <cuda_runtime.h>
#include <cuda_bf16.h>
#include <stdint.h>

#define T_STEPS 5
#define LH 128
#define NNV 16000
#define NCTA 125        // 16000/128

// ---------------- scratch (device globals; no runtime allocation) ----------------
__device__ float d_deg [NNV];                              // self-zeroing edge counts
__device__ float d_dinv[NNV];
__device__ float d_acc [NNV*T_STEPS];
__device__ __nv_bfloat16 d_y0b [(size_t)T_STEPS*NNV*LH];   // layer-0 hidden sequence
__device__ __nv_bfloat16 d_img0[512*200];                  // layer0 weight image [j][k], pitch 200
__device__ __nv_bfloat16 d_img1[512*264];                  // layer1, pitch 264
__device__ float d_biasC[1024];                            // [layer][gate*128+unit]

// ---------------- helpers ----------------
__device__ __forceinline__ float tanhfast(float x) {
    float y; asm("tanh.approx.f32 %0, %1;" : "=f"(y) : "f"(x)); return y;
}
__device__ __forceinline__ float sigmfast(float x) { return fmaf(tanhfast(0.5f*x), 0.5f, 0.5f); }

__device__ __forceinline__ uint32_t smem_u32(const void* p) {
    uint32_t a;
    asm("{ .reg .u64 t; cvta.to.shared.u64 t, %1; cvt.u32.u64 %0, t; }" : "=r"(a) : "l"(p));
    return a;
}
__device__ __forceinline__ void cp16(uint32_t d, const void* s) {
    asm volatile("cp.async.cg.shared.global [%0], [%1], 16;" :: "r"(d), "l"(s));
}
__device__ __forceinline__ void sts128(uint32_t a, uint4 v) {
    asm volatile("st.shared.v4.b32 [%0], {%1,%2,%3,%4};" :: "r"(a), "r"(v.x), "r"(v.y), "r"(v.z), "r"(v.w) : "memory");
}
__device__ __forceinline__ void ldsm4(uint32_t a, uint32_t& r0, uint32_t& r1, uint32_t& r2, uint32_t& r3) {
    asm volatile("ldmatrix.sync.aligned.m8n8.x4.shared.b16 {%0,%1,%2,%3}, [%4];"
                 : "=r"(r0), "=r"(r1), "=r"(r2), "=r"(r3) : "r"(a));
}
__device__ __forceinline__ void mma16816(float* d, const uint32_t* a, const uint32_t* b) {
    asm volatile("mma.sync.aligned.m16n8k16.row.col.f32.bf16.bf16.f32 "
        "{%0,%1,%2,%3}, {%4,%5,%6,%7}, {%8,%9}, {%0,%1,%2,%3};"
        : "+f"(d[0]), "+f"(d[1]), "+f"(d[2]), "+f"(d[3])
        : "r"(a[0]), "r"(a[1]), "r"(a[2]), "r"(a[3]), "r"(b[0]), "r"(b[1]));
}

// ---------------- prep: weight/bias images + edge-degree counting, ONE launch -----
// Gate-major-within-warp-slice column order:
//   j = ch*64 + wc*32 + gate*8 + cc  ->  unit = ch*16 + wc*8 + cc
// so each warp's four n8 MMA blocks are the 4 gates of the SAME 8 units
// (shuffle-free epilogue). deg starts at 0 (self-zeroed each call).
__global__ void k_prep(const float* __restrict__ Wih0, const float* __restrict__ Whh0,
                       const float* __restrict__ Wih1, const float* __restrict__ Whh1,
                       const float* __restrict__ bi0, const float* __restrict__ bh0,
                       const float* __restrict__ bi1, const float* __restrict__ bh1,
                       const int* __restrict__ dst, int E) {
    int gid = blockIdx.x*256 + threadIdx.x;

    // edge-degree counting (4-edge ILP)
    int e0 = gid*4;
#pragma unroll
    for (int j = 0; j < 4; j++) {
        int e = e0 + j;
        if (e < E) atomicAdd(&d_deg[dst[e]], 1.0f);
    }

    // combined biases, natural W-row order [gate*128+unit]
    if (gid < 1024) {
        int l = gid >> 9, w = gid & 511;
        d_biasC[gid] = l ? (bi1[w] + bh1[w]) : (bi0[w] + bh0[w]);
    }

    // weight images
    const int W0 = 512*192;
    if (gid < W0) {
        int k = gid % 192, j = gid / 192;
        int ch = j >> 6, wcl = (j >> 5) & 1, gt = (j >> 3) & 3, cc = j & 7;
        int u = ch*16 + wcl*8 + cc;
        float v = (k < 64) ? Wih0[(gt*LH + u)*64 + k] : Whh0[(gt*LH + u)*LH + (k - 64)];
        d_img0[j*200 + k] = __float2bfloat16(v);
    } else if (gid < W0 + 512*256) {
        int g2 = gid - W0;
        int k = g2 % 256, j = g2 / 256;
        int ch = j >> 6, wcl = (j >> 5) & 1, gt = (j >> 3) & 3, cc = j & 7;
        int u = ch*16 + wcl*8 + cc;
        float v = (k < 128) ? Wih1[(gt*LH + u)*LH + k] : Whh1[(gt*LH + u)*LH + (k - 128)];
        d_img1[j*264 + k] = __float2bfloat16(v);
    }
}

__global__ void k_dinv_accinit(const float* __restrict__ x, float* __restrict__ deg,
                               float* __restrict__ dinv, float* __restrict__ acc, int n) {
    int i = blockIdx.x*blockDim.x + threadIdx.x;
    if (i >= n) return;
    float di = rsqrtf(deg[i] + 1.0f);     // +1 = self-loop
    deg[i] = 0.f;                         // re-zero for next graph replay
    dinv[i] = di;
#pragma unroll
    for (int t = 0; t < T_STEPS; t++)
        acc[i*T_STEPS + t] = x[i*T_STEPS + t] * di;
}
__global__ void k_scatter(const int* __restrict__ src, const int* __restrict__ dst,
                          const float* __restrict__ x, const float* __restrict__ dinv,
                          float* __restrict__ acc, int E) {
    int e0 = (blockIdx.x*blockDim.x + threadIdx.x)*4;
#pragma unroll
    for (int j = 0; j < 4; j++) {
        int e = e0 + j;
        if (e < E) {
            int s = src[e], d = dst[e];
            float ds = dinv[s];
#pragma unroll
            for (int t = 0; t < T_STEPS; t++)
                atomicAdd(&acc[d*T_STEPS + t], x[s*T_STEPS + t] * ds);
        }
    }
}

// ---------------- one LSTM layer over this CTA's 128 rows -------------------------
template<int LAYER>
__device__ __forceinline__ void run_layer(char* smem, uint32_t sb,
                                          const float* gw, const float* gb, int m0s)
{
    constexpr int KIH  = LAYER ? 128 : 64;
    constexpr int KP   = KIH + LH + 8;          // 264 / 200
    constexpr int NK16 = (KIH + LH) / 16;       // 16 / 12
    constexpr int AB   = 128*KP*2;
    constexpr int CB   = 128*129*4;
    constexpr int BCH  = 64*KP*2;
    constexpr int OFF_C    = AB;
    constexpr int OFF_B    = AB + CB;
    constexpr int OFF_BIAS = OFF_B + 2*BCH;
    constexpr int OFF_GW   = OFF_BIAS + 2048;

    float* cS    = (float*)(smem + OFF_C);      // [128][129]
    float* sbias = (float*)(smem + OFF_BIAS);   // 512, [gate*128+unit]
    float* sgw   = (float*)(smem + OFF_GW);     // 64 gw + 64 gb

    const int tid = threadIdx.x, wid = tid >> 5, lane = tid & 31;
    const int g = lane >> 3, lr = lane & 7;
    const int wr = wid >> 1, wc = wid & 1;      // 4 row-groups x 2 col-halves
    const __nv_bfloat16* img = LAYER ? d_img1 : d_img0;

    if (LAYER == 0 && tid < 128) sgw[tid] = (tid < 64) ? gw[tid] : gb[tid - 64];
    for (int i = tid; i < 512; i += 256) sbias[i] = d_biasC[LAYER*512 + i];
    // zero only the h-columns of the A tile (h0 = 0) and c
    for (int i = tid; i < 128*16; i += 256) {
        int row = i >> 4, c8 = i & 15;
        *(uint4*)(smem + (size_t)(row*KP + KIH)*2 + c8*16) = make_uint4(0,0,0,0);
    }
    for (int i = tid; i < CB/16; i += 256) ((uint4*)(smem + OFF_C))[i] = make_uint4(0,0,0,0);
    __syncthreads();

    auto stage_ih = [&](int t) {
        if (LAYER == 0) {
#pragma unroll
            for (int it = 0; it < 4; it++) {            // feat cols 0..63 in-register
                int idx = tid + it*256;
                int row = idx >> 3, ch = idx & 7;
                int m = m0s + row;
                float av = d_acc[m*T_STEPS + t] * d_dinv[m];
                uint32_t w[4];
#pragma unroll
                for (int i = 0; i < 4; i++) {
                    int k = ch*8 + 2*i;
                    float f0 = fmaxf(fmaf(av, sgw[k],   sgw[64+k]),   0.f);
                    float f1 = fmaxf(fmaf(av, sgw[k+1], sgw[64+k+1]), 0.f);
                    __nv_bfloat162 b2 = __floats2bfloat162_rn(f0, f1);
                    w[i] = *reinterpret_cast<uint32_t*>(&b2);
                }
                sts128(sb + (uint32_t)((row*KP + ch*8)*2), make_uint4(w[0], w[1], w[2], w[3]));
            }
        } else {
            const __nv_bfloat16* src = d_y0b + (size_t)t*NNV*LH;
#pragma unroll
            for (int it = 0; it < 8; it++) {            // ih cols 0..127 via cp.async
                int idx = tid + it*256;
                int row = idx >> 4, ch = idx & 15;
                cp16(sb + (uint32_t)((row*KP + ch*8)*2), src + (size_t)(m0s + row)*LH + ch*8);
            }
            asm volatile("cp.async.commit_group;");
        }
    };
    auto issueB = [&](int ch, int bsel) {
        const __nv_bfloat16* src = img + ch*64*KP;
        uint32_t dst = sb + OFF_B + bsel*BCH;
        for (int i = tid; i < BCH/16; i += 256) cp16(dst + i*16, src + (size_t)i*8);
        asm volatile("cp.async.commit_group;");
    };

    stage_ih(0);
    issueB(0, 0);

    int buf = 0;
    for (int t = 0; t < T_STEPS; t++) {
        asm volatile("cp.async.wait_group 1;");      // ih for this step done
        __syncthreads();                             // h-col epilogue writes visible

        // A fragments for the whole step -> registers (32 rows/warp, 2 m16-groups)
        uint32_t afr[NK16][8];
        uint32_t aAddr0 = sb + (uint32_t)(((wr*32 + (g & 1)*8 + lr)*KP + (g >> 1)*8)*2);
#pragma unroll
        for (int s = 0; s < NK16; s++) {
            ldsm4(aAddr0 + s*32,                       afr[s][0], afr[s][1], afr[s][2], afr[s][3]);
            ldsm4(aAddr0 + (uint32_t)(16*KP*2) + s*32, afr[s][4], afr[s][5], afr[s][6], afr[s][7]);
        }
        __syncthreads();
        if (t + 1 < T_STEPS) stage_ih(t + 1);        // ih cols dead -> prefetch next step

        for (int ch = 0; ch < 8; ch++) {
            const bool last = (t == T_STEPS - 1 && ch == 7);
            if (!last) issueB((ch + 1) & 7, buf ^ 1);
            if (last) asm volatile("cp.async.wait_group 0;");
            else      asm volatile("cp.async.wait_group 1;");
            __syncthreads();

            float acc[2][4][4];
#pragma unroll
            for (int mt = 0; mt < 2; mt++)
#pragma unroll
                for (int nt = 0; nt < 4; nt++)
#pragma unroll
                    for (int i = 0; i < 4; i++) acc[mt][nt][i] = 0.f;

            // this warp's 32 cols (4 n8 blocks = 4 gates of 8 units)
            uint32_t bbase = sb + OFF_B + buf*BCH
                           + (uint32_t)(((wc*32 + (g >> 1)*8 + lr)*KP + (g & 1)*8)*2);
#pragma unroll
            for (int s = 0; s < NK16; s++) {
                uint32_t bB[2][4];
#pragma unroll
                for (int p = 0; p < 2; p++)
                    ldsm4(bbase + (uint32_t)(p*16*KP*2) + s*32, bB[p][0], bB[p][1], bB[p][2], bB[p][3]);
#pragma unroll
                for (int p = 0; p < 2; p++) {
                    mma16816(acc[0][2*p],   afr[s],     &bB[p][0]);
                    mma16816(acc[0][2*p+1], afr[s],     &bB[p][2]);
                    mma16816(acc[1][2*p],   afr[s] + 4, &bB[p][0]);
                    mma16816(acc[1][2*p+1], afr[s] + 4, &bB[p][2]);
                }
            }

            // epilogue: shuffle-free gate math (acc[mt][gate][q] = 4 gates, same unit)
            {
                const int cb = 2*(lane & 3);
                const int ub = ch*16 + wc*8 + cb;
#pragma unroll
                for (int mt = 0; mt < 2; mt++) {
                    const int r0 = wr*32 + mt*16 + (lane >> 2);
#pragma unroll
                    for (int q = 0; q < 4; q++) {
                        int rr = r0 + ((q >> 1) << 3);
                        int uu = ub + (q & 1);
                        float gi = acc[mt][0][q] + sbias[uu];
                        float gf = acc[mt][1][q] + sbias[128 + uu];
                        float gg = acc[mt][2][q] + sbias[256 + uu];
                        float go = acc[mt][3][q] + sbias[384 + uu];
                        float cold = cS[rr*129 + uu];
                        float cn = sigmfast(gf)*cold + sigmfast(gi)*tanhfast(gg);
                        cS[rr*129 + uu] = cn;
                        float hv = sigmfast(go)*tanhfast(cn);
                        *(__nv_bfloat16*)(smem + (size_t)(rr*KP + KIH + uu)*2) = __float2bfloat16(hv);
                    }
                }
            }
            __syncthreads();
            buf ^= 1;
        }

        // layer0: h tile -> global y0 (layer1 final h stays in smem for the fused head)
        if (LAYER == 0) {
            __nv_bfloat16* dst = d_y0b + (size_t)t*NNV*LH;
#pragma unroll
            for (int it = 0; it < 8; it++) {
                int idx = tid + it*256;
                int row = idx >> 4, c8 = idx & 15;
                uint4 v = *(uint4*)(smem + (size_t)(row*KP + KIH + c8*8)*2);
                *(uint4*)(dst + (size_t)(m0s + row)*LH + c8*8) = v;
            }
        }
    }
}

// ---------------- fused 2-layer LSTM + head: 125 CTAs x 128 rows -------------------
__global__ void __launch_bounds__(256, 1)
k_lstm_fused(const float* __restrict__ gw, const float* __restrict__ gb,
             const float* __restrict__ x,
             const float* __restrict__ pw1, const float* __restrict__ pb1,
             const float* __restrict__ pw2, const float* __restrict__ pb2,
             float* __restrict__ out)
{
    extern __shared__ char smem[];
    const uint32_t sb = smem_u32(smem);
    const int m0s = blockIdx.x*128;
    const int tid = threadIdx.x, wid = tid >> 5, lane = tid & 31;

    run_layer<0>(smem, sb, gw, gb, m0s);
    __threadfence();          // y0 STG visible to layer-1 cp.async reads
    __syncthreads();
    run_layer<1>(smem, sb, gw, gb, m0s);

    // ---- fused head: final h is in the layer-1 A-tile h-columns (bf16, smem) ----
    constexpr int KP1 = 264, KIH1 = 128;
    constexpr int OFF_HB = 128*KP1*2 + 128*129*4;            // dead B-buffer region
    float* w1s = (float*)(smem + OFF_HB);                    // [128][65]
    float* w2s = (float*)(smem + OFF_HB + 128*65*4);         // 64
    float* b1s = w2s + 64;                                   // 64

    for (int idx = tid; idx < 64*128; idx += 256) {          // pw1 (64,128) -> [k][j]
        int j = idx >> 7, k = idx & 127;
        w1s[k*65 + j] = pw1[idx];
    }
    if (tid < 64) { w2s[tid] = pw2[tid]; b1s[tid] = pb1[tid]; }
    __syncthreads();

    const float pb2v = pb2[0];
#pragma unroll 1
    for (int r = 0; r < 16; r++) {                           // each warp: 16 rows
        int row = wid*16 + r;
        int m = m0s + row;
        const char* hrow = smem + (size_t)(row*KP1 + KIH1)*2;
        float s0 = b1s[lane], s1 = b1s[lane + 32];
#pragma unroll
        for (int k4 = 0; k4 < 32; k4++) {                    // 4 h values per iter
            uint2 hv = *(const uint2*)(hrow + k4*8);
            __nv_bfloat162 h01 = *reinterpret_cast<__nv_bfloat162*>(&hv.x);
            __nv_bfloat162 h23 = *reinterpret_cast<__nv_bfloat162*>(&hv.y);
            float f0 = __bfloat162float(h01.x), f1 = __bfloat162float(h01.y);
            float f2 = __bfloat162float(h23.x), f3 = __bfloat162float(h23.y);
            const float* wk = w1s + (k4*4)*65;
            s0 = fmaf(f0, wk[lane],        s0);
            s1 = fmaf(f0, wk[lane+32],     s1);
            s0 = fmaf(f1, wk[65+lane],     s0);
            s1 = fmaf(f1, wk[65+lane+32],  s1);
            s0 = fmaf(f2, wk[130+lane],    s0);
            s1 = fmaf(f2, wk[130+lane+32], s1);
            s0 = fmaf(f3, wk[195+lane],    s0);
            s1 = fmaf(f3, wk[195+lane+32], s1);
        }
        float part = fmaxf(s0, 0.f)*w2s[lane] + fmaxf(s1, 0.f)*w2s[lane+32];
#pragma unroll
        for (int o = 16; o; o >>= 1) part += __shfl_xor_sync(0xffffffffu, part, o);
        if (lane == 0) out[m] = part + pb2v + x[m*T_STEPS + (T_STEPS-1)];
    }
}

// ---------------- launcher ----------------
extern "C" void kernel_launch(void* const* d_in, const int* in_sizes, int n_in,
                              void* d_out, int out_size) {
    const float* x    = (const float*)d_in[0];
    const int*   ei   = (const int*)  d_in[1];
    const float* gw   = (const float*)d_in[2];
    const float* gb   = (const float*)d_in[3];
    const float* wih0 = (const float*)d_in[4];
    const float* whh0 = (const float*)d_in[5];
    const float* bih0 = (const float*)d_in[6];
    const float* bhh0 = (const float*)d_in[7];
    const float* wih1 = (const float*)d_in[8];
    const float* whh1 = (const float*)d_in[9];
    const float* bih1 = (const float*)d_in[10];
    const float* bhh1 = (const float*)d_in[11];
    const float* pw1  = (const float*)d_in[12];
    const float* pb1  = (const float*)d_in[13];
    const float* pw2  = (const float*)d_in[14];
    const float* pb2  = (const float*)d_in[15];
    float* out = (float*)d_out;

    const int NN = in_sizes[0] / T_STEPS;   // 16000
    const int E  = in_sizes[1] / 2;         // 256000
    const int* src = ei;
    const int* dst = ei + E;

    float *p_deg, *p_dinv, *p_acc;
    cudaGetSymbolAddress((void**)&p_deg,  d_deg);
    cudaGetSymbolAddress((void**)&p_dinv, d_dinv);
    cudaGetSymbolAddress((void**)&p_acc,  d_acc);

    // dynamic smem sized for layer1 (worst case): A + c + 2*Bchunk + bias + gwgb
    const int SMB = 128*264*2 + 128*129*4 + 2*64*264*2 + 2048 + 512;   // 203776
    cudaFuncSetAttribute(k_lstm_fused, cudaFuncAttributeMaxDynamicSharedMemorySize, SMB);

    // prep (weights + biases + edge-degree counting), single launch
    const int prepThreads = 512*192 + 512*256;
    k_prep<<<(prepThreads + 255)/256, 256>>>(wih0, whh0, wih1, whh1,
                                             bih0, bhh0, bih1, bhh1, dst, E);

    // GCN scalar aggregation
    k_dinv_accinit<<<(NN  + 255)/256, 256>>>(x, p_deg, p_dinv, p_acc, NN);
    k_scatter     <<<(E/4 + 255)/256, 256>>>(src, dst, x, p_dinv, p_acc, E);

    // both LSTM layers + head, fused
    k_lstm_fused<<<NCTA, 256, SMB>>>(gw, gb, x, pw1, pb1, pw2, pb2, out);
}

// round 15
// speedup vs baseline: 1.0177x; 1.0177x over previous
#include <cuda_runtime.h>
#include <cuda_bf16.h>
#include <stdint.h>

#define T_STEPS 5
#define LH 128
#define NNV 16000
#define NCTA 125        // 16000/128

// ---------------- scratch (device globals; no runtime allocation) ----------------
__device__ float d_deg [NNV];                              // self-zeroing edge counts
__device__ float d_dinv[NNV];
__device__ float d_acc [NNV*T_STEPS];
__device__ __nv_bfloat16 d_y0b [(size_t)T_STEPS*NNV*LH];   // layer-0 hidden sequence
__device__ __nv_bfloat16 d_img0[512*200];                  // layer0 weight image [j][k], pitch 200
__device__ __nv_bfloat16 d_img1[512*264];                  // layer1, pitch 264
__device__ float d_biasC[1024];                            // [layer][gate*128+unit]

// ---------------- helpers ----------------
__device__ __forceinline__ float tanhfast(float x) {
    float y; asm("tanh.approx.f32 %0, %1;" : "=f"(y) : "f"(x)); return y;
}
__device__ __forceinline__ float sigmfast(float x) { return fmaf(tanhfast(0.5f*x), 0.5f, 0.5f); }

__device__ __forceinline__ uint32_t smem_u32(const void* p) {
    uint32_t a;
    asm("{ .reg .u64 t; cvta.to.shared.u64 t, %1; cvt.u32.u64 %0, t; }" : "=r"(a) : "l"(p));
    return a;
}
__device__ __forceinline__ void cp16(uint32_t d, const void* s) {
    asm volatile("cp.async.cg.shared.global [%0], [%1], 16;" :: "r"(d), "l"(s));
}
__device__ __forceinline__ void sts128(uint32_t a, uint4 v) {
    asm volatile("st.shared.v4.b32 [%0], {%1,%2,%3,%4};" :: "r"(a), "r"(v.x), "r"(v.y), "r"(v.z), "r"(v.w) : "memory");
}
__device__ __forceinline__ void ldsm4(uint32_t a, uint32_t& r0, uint32_t& r1, uint32_t& r2, uint32_t& r3) {
    asm volatile("ldmatrix.sync.aligned.m8n8.x4.shared.b16 {%0,%1,%2,%3}, [%4];"
                 : "=r"(r0), "=r"(r1), "=r"(r2), "=r"(r3) : "r"(a));
}
__device__ __forceinline__ void mma16816(float* d, const uint32_t* a, const uint32_t* b) {
    asm volatile("mma.sync.aligned.m16n8k16.row.col.f32.bf16.bf16.f32 "
        "{%0,%1,%2,%3}, {%4,%5,%6,%7}, {%8,%9}, {%0,%1,%2,%3};"
        : "+f"(d[0]), "+f"(d[1]), "+f"(d[2]), "+f"(d[3])
        : "r"(a[0]), "r"(a[1]), "r"(a[2]), "r"(a[3]), "r"(b[0]), "r"(b[1]));
}

// ---------------- prep: weight/bias images + edge-degree counting, ONE launch -----
// Gate-major-within-warp-slice column order:
//   j = ch*64 + wc*32 + gate*8 + cc  ->  unit = ch*16 + wc*8 + cc
// so each warp's four n8 MMA blocks are the 4 gates of the SAME 8 units
// (shuffle-free epilogue). deg starts at 0 (self-zeroed each call).
__global__ void k_prep(const float* __restrict__ Wih0, const float* __restrict__ Whh0,
                       const float* __restrict__ Wih1, const float* __restrict__ Whh1,
                       const float* __restrict__ bi0, const float* __restrict__ bh0,
                       const float* __restrict__ bi1, const float* __restrict__ bh1,
                       const int* __restrict__ dst, int E) {
    int gid = blockIdx.x*256 + threadIdx.x;

    // edge-degree counting (4-edge ILP)
    int e0 = gid*4;
#pragma unroll
    for (int j = 0; j < 4; j++) {
        int e = e0 + j;
        if (e < E) atomicAdd(&d_deg[dst[e]], 1.0f);
    }

    // combined biases, natural W-row order [gate*128+unit]
    if (gid < 1024) {
        int l = gid >> 9, w = gid & 511;
        d_biasC[gid] = l ? (bi1[w] + bh1[w]) : (bi0[w] + bh0[w]);
    }

    // weight images
    const int W0 = 512*192;
    if (gid < W0) {
        int k = gid % 192, j = gid / 192;
        int ch = j >> 6, wcl = (j >> 5) & 1, gt = (j >> 3) & 3, cc = j & 7;
        int u = ch*16 + wcl*8 + cc;
        float v = (k < 64) ? Wih0[(gt*LH + u)*64 + k] : Whh0[(gt*LH + u)*LH + (k - 64)];
        d_img0[j*200 + k] = __float2bfloat16(v);
    } else if (gid < W0 + 512*256) {
        int g2 = gid - W0;
        int k = g2 % 256, j = g2 / 256;
        int ch = j >> 6, wcl = (j >> 5) & 1, gt = (j >> 3) & 3, cc = j & 7;
        int u = ch*16 + wcl*8 + cc;
        float v = (k < 128) ? Wih1[(gt*LH + u)*LH + k] : Whh1[(gt*LH + u)*LH + (k - 128)];
        d_img1[j*264 + k] = __float2bfloat16(v);
    }
}

__global__ void k_dinv_accinit(const float* __restrict__ x, float* __restrict__ deg,
                               float* __restrict__ dinv, float* __restrict__ acc, int n) {
    int i = blockIdx.x*blockDim.x + threadIdx.x;
    if (i >= n) return;
    float di = rsqrtf(deg[i] + 1.0f);     // +1 = self-loop
    deg[i] = 0.f;                         // re-zero for next graph replay
    dinv[i] = di;
#pragma unroll
    for (int t = 0; t < T_STEPS; t++)
        acc[i*T_STEPS + t] = x[i*T_STEPS + t] * di;
}
__global__ void k_scatter(const int* __restrict__ src, const int* __restrict__ dst,
                          const float* __restrict__ x, const float* __restrict__ dinv,
                          float* __restrict__ acc, int E) {
    int e0 = (blockIdx.x*blockDim.x + threadIdx.x)*4;
#pragma unroll
    for (int j = 0; j < 4; j++) {
        int e = e0 + j;
        if (e < E) {
            int s = src[e], d = dst[e];
            float ds = dinv[s];
#pragma unroll
            for (int t = 0; t < T_STEPS; t++)
                atomicAdd(&acc[d*T_STEPS + t], x[s*T_STEPS + t] * ds);
        }
    }
}

// ---------------- one LSTM layer over this CTA's 128 rows -------------------------
// Single-barrier chunk loop: issueB is ordered AFTER the chunk sync, so the
// cp.async write into buf^1 is provably after all warps' reads of it (they
// passed this sync having completed the previous chunk's MMA). Epilogue of a
// slow warp overlaps the next-chunk MMA of a fast warp.
template<int LAYER>
__device__ __forceinline__ void run_layer(char* smem, uint32_t sb,
                                          const float* gw, const float* gb, int m0s)
{
    constexpr int KIH  = LAYER ? 128 : 64;
    constexpr int KP   = KIH + LH + 8;          // 264 / 200
    constexpr int NK16 = (KIH + LH) / 16;       // 16 / 12
    constexpr int AB   = 128*KP*2;
    constexpr int CB   = 128*129*4;
    constexpr int BCH  = 64*KP*2;
    constexpr int OFF_C    = AB;
    constexpr int OFF_B    = AB + CB;
    constexpr int OFF_BIAS = OFF_B + 2*BCH;
    constexpr int OFF_GW   = OFF_BIAS + 2048;

    float* cS    = (float*)(smem + OFF_C);      // [128][129]
    float* sbias = (float*)(smem + OFF_BIAS);   // 512, [gate*128+unit]
    float* sgw   = (float*)(smem + OFF_GW);     // 64 gw + 64 gb

    const int tid = threadIdx.x, wid = tid >> 5, lane = tid & 31;
    const int g = lane >> 3, lr = lane & 7;
    const int wr = wid >> 1, wc = wid & 1;      // 4 row-groups x 2 col-halves
    const __nv_bfloat16* img = LAYER ? d_img1 : d_img0;

    if (LAYER == 0 && tid < 128) sgw[tid] = (tid < 64) ? gw[tid] : gb[tid - 64];
    for (int i = tid; i < 512; i += 256) sbias[i] = d_biasC[LAYER*512 + i];
    // zero only the h-columns of the A tile (h0 = 0) and c
    for (int i = tid; i < 128*16; i += 256) {
        int row = i >> 4, c8 = i & 15;
        *(uint4*)(smem + (size_t)(row*KP + KIH)*2 + c8*16) = make_uint4(0,0,0,0);
    }
    for (int i = tid; i < CB/16; i += 256) ((uint4*)(smem + OFF_C))[i] = make_uint4(0,0,0,0);
    __syncthreads();

    // stage_ih: NO own commit — layer-1 copies ride in the next issueB group.
    auto stage_ih = [&](int t) {
        if (LAYER == 0) {
#pragma unroll
            for (int it = 0; it < 4; it++) {            // feat cols 0..63 in-register
                int idx = tid + it*256;
                int row = idx >> 3, ch = idx & 7;
                int m = m0s + row;
                float av = d_acc[m*T_STEPS + t] * d_dinv[m];
                uint32_t w[4];
#pragma unroll
                for (int i = 0; i < 4; i++) {
                    int k = ch*8 + 2*i;
                    float f0 = fmaxf(fmaf(av, sgw[k],   sgw[64+k]),   0.f);
                    float f1 = fmaxf(fmaf(av, sgw[k+1], sgw[64+k+1]), 0.f);
                    __nv_bfloat162 b2 = __floats2bfloat162_rn(f0, f1);
                    w[i] = *reinterpret_cast<uint32_t*>(&b2);
                }
                sts128(sb + (uint32_t)((row*KP + ch*8)*2), make_uint4(w[0], w[1], w[2], w[3]));
            }
        } else {
            const __nv_bfloat16* src = d_y0b + (size_t)t*NNV*LH;
#pragma unroll
            for (int it = 0; it < 8; it++) {            // ih cols 0..127 via cp.async
                int idx = tid + it*256;
                int row = idx >> 4, ch = idx & 15;
                cp16(sb + (uint32_t)((row*KP + ch*8)*2), src + (size_t)(m0s + row)*LH + ch*8);
            }
        }
    };
    auto issueB = [&](int ch, int bsel) {
        const __nv_bfloat16* src = img + ch*64*KP;
        uint32_t dst = sb + OFF_B + bsel*BCH;
        for (int i = tid; i < BCH/16; i += 256) cp16(dst + i*16, src + (size_t)i*8);
        asm volatile("cp.async.commit_group;");
    };

    stage_ih(0);
    issueB(0, 0);      // commit includes layer-1 stage_ih(0) copies

    int buf = 0;
    for (int t = 0; t < T_STEPS; t++) {
        asm volatile("cp.async.wait_group 0;");      // ih + B chunk0 for this step done
        __syncthreads();                             // h-col epilogue writes visible

        // A fragments for the whole step -> registers (32 rows/warp, 2 m16-groups)
        uint32_t afr[NK16][8];
        uint32_t aAddr0 = sb + (uint32_t)(((wr*32 + (g & 1)*8 + lr)*KP + (g >> 1)*8)*2);
#pragma unroll
        for (int s = 0; s < NK16; s++) {
            ldsm4(aAddr0 + s*32,                       afr[s][0], afr[s][1], afr[s][2], afr[s][3]);
            ldsm4(aAddr0 + (uint32_t)(16*KP*2) + s*32, afr[s][4], afr[s][5], afr[s][6], afr[s][7]);
        }
        __syncthreads();                             // frags loaded before ih overwrite
        if (t + 1 < T_STEPS) stage_ih(t + 1);        // copies join next issueB group

        for (int ch = 0; ch < 8; ch++) {
            asm volatile("cp.async.wait_group 0;");  // B[buf] (and older) complete
            __syncthreads();                         // all reads of buf^1 finished
            const bool last = (t == T_STEPS - 1 && ch == 7);
            if (!last) issueB((ch + 1) & 7, buf ^ 1);

            float acc[2][4][4];
#pragma unroll
            for (int mt = 0; mt < 2; mt++)
#pragma unroll
                for (int nt = 0; nt < 4; nt++)
#pragma unroll
                    for (int i = 0; i < 4; i++) acc[mt][nt][i] = 0.f;

            // this warp's 32 cols (4 n8 blocks = 4 gates of 8 units)
            uint32_t bbase = sb + OFF_B + buf*BCH
                           + (uint32_t)(((wc*32 + (g >> 1)*8 + lr)*KP + (g & 1)*8)*2);
#pragma unroll
            for (int s = 0; s < NK16; s++) {
                uint32_t bB[2][4];
#pragma unroll
                for (int p = 0; p < 2; p++)
                    ldsm4(bbase + (uint32_t)(p*16*KP*2) + s*32, bB[p][0], bB[p][1], bB[p][2], bB[p][3]);
#pragma unroll
                for (int p = 0; p < 2; p++) {
                    mma16816(acc[0][2*p],   afr[s],     &bB[p][0]);
                    mma16816(acc[0][2*p+1], afr[s],     &bB[p][2]);
                    mma16816(acc[1][2*p],   afr[s] + 4, &bB[p][0]);
                    mma16816(acc[1][2*p+1], afr[s] + 4, &bB[p][2]);
                }
            }

            // epilogue: shuffle-free gate math; c is same-thread, h-cols read only
            // after the next step-start sync -> no barrier needed here.
            {
                const int cb = 2*(lane & 3);
                const int ub = ch*16 + wc*8 + cb;
#pragma unroll
                for (int mt = 0; mt < 2; mt++) {
                    const int r0 = wr*32 + mt*16 + (lane >> 2);
#pragma unroll
                    for (int q = 0; q < 4; q++) {
                        int rr = r0 + ((q >> 1) << 3);
                        int uu = ub + (q & 1);
                        float gi = acc[mt][0][q] + sbias[uu];
                        float gf = acc[mt][1][q] + sbias[128 + uu];
                        float gg = acc[mt][2][q] + sbias[256 + uu];
                        float go = acc[mt][3][q] + sbias[384 + uu];
                        float cold = cS[rr*129 + uu];
                        float cn = sigmfast(gf)*cold + sigmfast(gi)*tanhfast(gg);
                        cS[rr*129 + uu] = cn;
                        float hv = sigmfast(go)*tanhfast(cn);
                        *(__nv_bfloat16*)(smem + (size_t)(rr*KP + KIH + uu)*2) = __float2bfloat16(hv);
                    }
                }
            }
            buf ^= 1;
        }

        // layer0: h tile -> global y0 (needs all warps' epilogues of this step)
        if (LAYER == 0) {
            __syncthreads();
            __nv_bfloat16* dst = d_y0b + (size_t)t*NNV*LH;
#pragma unroll
            for (int it = 0; it < 8; it++) {
                int idx = tid + it*256;
                int row = idx >> 4, c8 = idx & 15;
                uint4 v = *(uint4*)(smem + (size_t)(row*KP + KIH + c8*8)*2);
                *(uint4*)(dst + (size_t)(m0s + row)*LH + c8*8) = v;
            }
        }
    }
    __syncthreads();    // all warps done (B region dead, h-cols final) before caller reuses smem
}

// ---------------- fused 2-layer LSTM + head: 125 CTAs x 128 rows -------------------
__global__ void __launch_bounds__(256, 1)
k_lstm_fused(const float* __restrict__ gw, const float* __restrict__ gb,
             const float* __restrict__ x,
             const float* __restrict__ pw1, const float* __restrict__ pb1,
             const float* __restrict__ pw2, const float* __restrict__ pb2,
             float* __restrict__ out)
{
    extern __shared__ char smem[];
    const uint32_t sb = smem_u32(smem);
    const int m0s = blockIdx.x*128;
    const int tid = threadIdx.x, wid = tid >> 5, lane = tid & 31;

    run_layer<0>(smem, sb, gw, gb, m0s);
    __threadfence();          // y0 STG visible to layer-1 cp.async reads
    __syncthreads();
    run_layer<1>(smem, sb, gw, gb, m0s);

    // ---- fused head: final h is in the layer-1 A-tile h-columns (bf16, smem) ----
    constexpr int KP1 = 264, KIH1 = 128;
    constexpr int OFF_HB = 128*KP1*2 + 128*129*4;            // dead B-buffer region
    float* w1s = (float*)(smem + OFF_HB);                    // [128][65]
    float* w2s = (float*)(smem + OFF_HB + 128*65*4);         // 64
    float* b1s = w2s + 64;                                   // 64

    for (int idx = tid; idx < 64*128; idx += 256) {          // pw1 (64,128) -> [k][j]
        int j = idx >> 7, k = idx & 127;
        w1s[k*65 + j] = pw1[idx];
    }
    if (tid < 64) { w2s[tid] = pw2[tid]; b1s[tid] = pb1[tid]; }
    __syncthreads();

    const float pb2v = pb2[0];
#pragma unroll 1
    for (int r = 0; r < 16; r++) {                           // each warp: 16 rows
        int row = wid*16 + r;
        int m = m0s + row;
        const char* hrow = smem + (size_t)(row*KP1 + KIH1)*2;
        float s0 = b1s[lane], s1 = b1s[lane + 32];
#pragma unroll
        for (int k4 = 0; k4 < 32; k4++) {                    // 4 h values per iter
            uint2 hv = *(const uint2*)(hrow + k4*8);
            __nv_bfloat162 h01 = *reinterpret_cast<__nv_bfloat162*>(&hv.x);
            __nv_bfloat162 h23 = *reinterpret_cast<__nv_bfloat162*>(&hv.y);
            float f0 = __bfloat162float(h01.x), f1 = __bfloat162float(h01.y);
            float f2 = __bfloat162float(h23.x), f3 = __bfloat162float(h23.y);
            const float* wk = w1s + (k4*4)*65;
            s0 = fmaf(f0, wk[lane],        s0);
            s1 = fmaf(f0, wk[lane+32],     s1);
            s0 = fmaf(f1, wk[65+lane],     s0);
            s1 = fmaf(f1, wk[65+lane+32],  s1);
            s0 = fmaf(f2, wk[130+lane],    s0);
            s1 = fmaf(f2, wk[130+lane+32], s1);
            s0 = fmaf(f3, wk[195+lane],    s0);
            s1 = fmaf(f3, wk[195+lane+32], s1);
        }
        float part = fmaxf(s0, 0.f)*w2s[lane] + fmaxf(s1, 0.f)*w2s[lane+32];
#pragma unroll
        for (int o = 16; o; o >>= 1) part += __shfl_xor_sync(0xffffffffu, part, o);
        if (lane == 0) out[m] = part + pb2v + x[m*T_STEPS + (T_STEPS-1)];
    }
}

// ---------------- launcher ----------------
extern "C" void kernel_launch(void* const* d_in, const int* in_sizes, int n_in,
                              void* d_out, int out_size) {
    const float* x    = (const float*)d_in[0];
    const int*   ei   = (const int*)  d_in[1];
    const float* gw   = (const float*)d_in[2];
    const float* gb   = (const float*)d_in[3];
    const float* wih0 = (const float*)d_in[4];
    const float* whh0 = (const float*)d_in[5];
    const float* bih0 = (const float*)d_in[6];
    const float* bhh0 = (const float*)d_in[7];
    const float* wih1 = (const float*)d_in[8];
    const float* whh1 = (const float*)d_in[9];
    const float* bih1 = (const float*)d_in[10];
    const float* bhh1 = (const float*)d_in[11];
    const float* pw1  = (const float*)d_in[12];
    const float* pb1  = (const float*)d_in[13];
    const float* pw2  = (const float*)d_in[14];
    const float* pb2  = (const float*)d_in[15];
    float* out = (float*)d_out;

    const int NN = in_sizes[0] / T_STEPS;   // 16000
    const int E  = in_sizes[1] / 2;         // 256000
    const int* src = ei;
    const int* dst = ei + E;

    float *p_deg, *p_dinv, *p_acc;
    cudaGetSymbolAddress((void**)&p_deg,  d_deg);
    cudaGetSymbolAddress((void**)&p_dinv, d_dinv);
    cudaGetSymbolAddress((void**)&p_acc,  d_acc);

    // dynamic smem sized for layer1 (worst case): A + c + 2*Bchunk + bias + gwgb
    const int SMB = 128*264*2 + 128*129*4 + 2*64*264*2 + 2048 + 512;   // 203776
    cudaFuncSetAttribute(k_lstm_fused, cudaFuncAttributeMaxDynamicSharedMemorySize, SMB);

    // prep (weights + biases + edge-degree counting), single launch
    const int prepThreads = 512*192 + 512*256;
    k_prep<<<(prepThreads + 255)/256, 256>>>(wih0, whh0, wih1, whh1,
                                             bih0, bhh0, bih1, bhh1, dst, E);

    // GCN scalar aggregation
    k_dinv_accinit<<<(NN  + 255)/256, 256>>>(x, p_deg, p_dinv, p_acc, NN);
    k_scatter     <<<(E/4 + 255)/256, 256>>>(src, dst, x, p_dinv, p_acc, E);

    // both LSTM layers + head, fused
    k_lstm_fused<<<NCTA, 256, SMB>>>(gw, gb, x, pw1, pb1, pw2, pb2, out);
}